// round 1
// baseline (speedup 1.0000x reference)
#include <cuda_runtime.h>

#define Tt 8192
#define Kk 2
#define Hh 1024
#define Ii 2816
#define Ee 8
#define TKp (Tt * Kk)      // 16384 pairs
#define I2 (2 * Ii)        // 5632

// Scratch (device globals — no allocation allowed)
__device__ float g_h[(size_t)TKp * Ii];   // per-pair intermediate h, 184 MB
__device__ int   g_cnt[Ee];
__device__ int   g_list[Ee * TKp];        // pair ids per expert

// ---------------------------------------------------------------------------
__global__ void zero_out_kernel(float4* out) {
    int i = blockIdx.x * blockDim.x + threadIdx.x;
    out[i] = make_float4(0.f, 0.f, 0.f, 0.f);
}

__global__ void zero_cnt_kernel() {
    if (threadIdx.x < Ee) g_cnt[threadIdx.x] = 0;
}

__global__ void route_kernel(const int* __restrict__ routing) {
    int p = blockIdx.x * blockDim.x + threadIdx.x;
    if (p >= TKp) return;
    int e = routing[p];
    int pos = atomicAdd(&g_cnt[e], 1);
    g_list[e * TKp + pos] = p;
}

// ---------------------------------------------------------------------------
// GEMM1: for expert e, rows = gathered tokens, cols = I-tile of h.
// Computes gate and up simultaneously, writes h = silu(gate)*up.
// Block tile: 128 rows x 64 cols, BK=16. 256 threads, 8x4 per thread (x2 accum).
__global__ __launch_bounds__(256, 2)
void gemm1_kernel(const float* __restrict__ hidden, const float* __restrict__ w13) {
    const int e = blockIdx.z;
    const int cnt = g_cnt[e];
    const int row0 = blockIdx.y * 128;
    if (row0 >= cnt) return;
    const int c0 = blockIdx.x * 64;
    const int tid = threadIdx.x;

    __shared__ float As[16][128];
    __shared__ float Bg[16][64];
    __shared__ float Bu[16][64];
    __shared__ int   sp[128];

    if (tid < 128) {
        int r = row0 + tid;
        sp[tid] = (r < cnt) ? g_list[e * TKp + r] : -1;
    }
    __syncthreads();

    // A loads: 128 rows x 16 k, each thread 8 floats (2 x float4)
    const int a_row = tid & 127;
    const int a_k   = (tid >> 7) * 8;
    const int pa = sp[a_row];
    const float* a_src = hidden + (size_t)(pa < 0 ? 0 : (pa >> 1)) * Hh; // token = p/K

    // B loads: 16 x 64, one float4 per thread (gate and up)
    const int b_kk = tid >> 4;
    const int b_cc = (tid & 15) * 4;
    const float* wg = w13 + (size_t)e * Hh * I2 + (size_t)b_kk * I2 + c0 + b_cc;
    const float* wu = wg + Ii;

    const int ty = tid >> 4;   // 0..15 -> row group of 8
    const int tx = tid & 15;   // 0..15 -> col group of 4

    float accg[8][4], accu[8][4];
#pragma unroll
    for (int i = 0; i < 8; i++)
#pragma unroll
        for (int j = 0; j < 4; j++) { accg[i][j] = 0.f; accu[i][j] = 0.f; }

    for (int k0 = 0; k0 < Hh; k0 += 16) {
        float4 a0 = *(const float4*)(a_src + k0 + a_k);
        float4 a1 = *(const float4*)(a_src + k0 + a_k + 4);
        float4 bg = *(const float4*)(wg + (size_t)k0 * I2);
        float4 bu = *(const float4*)(wu + (size_t)k0 * I2);
        As[a_k + 0][a_row] = a0.x; As[a_k + 1][a_row] = a0.y;
        As[a_k + 2][a_row] = a0.z; As[a_k + 3][a_row] = a0.w;
        As[a_k + 4][a_row] = a1.x; As[a_k + 5][a_row] = a1.y;
        As[a_k + 6][a_row] = a1.z; As[a_k + 7][a_row] = a1.w;
        *(float4*)&Bg[b_kk][b_cc] = bg;
        *(float4*)&Bu[b_kk][b_cc] = bu;
        __syncthreads();
#pragma unroll
        for (int kk = 0; kk < 16; ++kk) {
            float ar[8], bgr[4], bur[4];
            *(float4*)(ar)     = *(const float4*)&As[kk][ty * 8];
            *(float4*)(ar + 4) = *(const float4*)&As[kk][ty * 8 + 4];
            *(float4*)(bgr)    = *(const float4*)&Bg[kk][tx * 4];
            *(float4*)(bur)    = *(const float4*)&Bu[kk][tx * 4];
#pragma unroll
            for (int i = 0; i < 8; i++)
#pragma unroll
                for (int j = 0; j < 4; j++) {
                    accg[i][j] += ar[i] * bgr[j];
                    accu[i][j] += ar[i] * bur[j];
                }
        }
        __syncthreads();
    }

    // Epilogue: h = silu(gate) * up
#pragma unroll
    for (int i = 0; i < 8; i++) {
        int p = sp[ty * 8 + i];
        if (p < 0) continue;
        float4 hv;
        float g, u;
        g = accg[i][0]; u = accu[i][0]; hv.x = (g / (1.f + __expf(-g))) * u;
        g = accg[i][1]; u = accu[i][1]; hv.y = (g / (1.f + __expf(-g))) * u;
        g = accg[i][2]; u = accu[i][2]; hv.z = (g / (1.f + __expf(-g))) * u;
        g = accg[i][3]; u = accu[i][3]; hv.w = (g / (1.f + __expf(-g))) * u;
        *(float4*)(g_h + (size_t)p * Ii + c0 + tx * 4) = hv;
    }
}

// ---------------------------------------------------------------------------
// GEMM2: out[t] += coeff[p] * (h[p] @ w2[e]).
// Block tile: 128 rows x 128 cols, BK=16. 256 threads, 8x8 per thread.
__global__ __launch_bounds__(256, 2)
void gemm2_kernel(const float* __restrict__ rw, const float* __restrict__ w2,
                  float* __restrict__ out) {
    const int e = blockIdx.z;
    const int cnt = g_cnt[e];
    const int row0 = blockIdx.y * 128;
    if (row0 >= cnt) return;
    const int c0 = blockIdx.x * 128;
    const int tid = threadIdx.x;

    __shared__ float As[16][128];
    __shared__ float Bs[16][128];
    __shared__ int   sp[128];

    if (tid < 128) {
        int r = row0 + tid;
        sp[tid] = (r < cnt) ? g_list[e * TKp + r] : -1;
    }
    __syncthreads();

    const int a_row = tid & 127;
    const int a_k   = (tid >> 7) * 8;
    const int pa = sp[a_row];
    const float* a_src = g_h + (size_t)(pa < 0 ? 0 : pa) * Ii;

    // B loads: 16 x 128, two float4 per thread
    const int b_kk = tid >> 4;
    const int b_cc = (tid & 15) * 8;
    const float* wB = w2 + (size_t)e * Ii * Hh + (size_t)b_kk * Hh + c0 + b_cc;

    const int ty = tid >> 4;
    const int tx = tid & 15;

    float acc[8][8];
#pragma unroll
    for (int i = 0; i < 8; i++)
#pragma unroll
        for (int j = 0; j < 8; j++) acc[i][j] = 0.f;

    for (int k0 = 0; k0 < Ii; k0 += 16) {
        float4 a0 = *(const float4*)(a_src + k0 + a_k);
        float4 a1 = *(const float4*)(a_src + k0 + a_k + 4);
        float4 b0 = *(const float4*)(wB + (size_t)k0 * Hh);
        float4 b1 = *(const float4*)(wB + (size_t)k0 * Hh + 4);
        As[a_k + 0][a_row] = a0.x; As[a_k + 1][a_row] = a0.y;
        As[a_k + 2][a_row] = a0.z; As[a_k + 3][a_row] = a0.w;
        As[a_k + 4][a_row] = a1.x; As[a_k + 5][a_row] = a1.y;
        As[a_k + 6][a_row] = a1.z; As[a_k + 7][a_row] = a1.w;
        *(float4*)&Bs[b_kk][b_cc]     = b0;
        *(float4*)&Bs[b_kk][b_cc + 4] = b1;
        __syncthreads();
#pragma unroll
        for (int kk = 0; kk < 16; ++kk) {
            float ar[8], br[8];
            *(float4*)(ar)     = *(const float4*)&As[kk][ty * 8];
            *(float4*)(ar + 4) = *(const float4*)&As[kk][ty * 8 + 4];
            *(float4*)(br)     = *(const float4*)&Bs[kk][tx * 8];
            *(float4*)(br + 4) = *(const float4*)&Bs[kk][tx * 8 + 4];
#pragma unroll
            for (int i = 0; i < 8; i++)
#pragma unroll
                for (int j = 0; j < 8; j++) acc[i][j] += ar[i] * br[j];
        }
        __syncthreads();
    }

    // Epilogue: atomic scatter-add with router coefficient
#pragma unroll
    for (int i = 0; i < 8; i++) {
        int p = sp[ty * 8 + i];
        if (p < 0) continue;
        int t = p >> 1;                 // token = p / K
        float c = rw[p];
        float* o = out + (size_t)t * Hh + c0 + tx * 8;
#pragma unroll
        for (int j = 0; j < 8; j++) atomicAdd(o + j, c * acc[i][j]);
    }
}

// ---------------------------------------------------------------------------
extern "C" void kernel_launch(void* const* d_in, const int* in_sizes, int n_in,
                              void* d_out, int out_size) {
    const float* hidden  = (const float*)d_in[0];
    const int*   routing = (const int*)d_in[1];
    const float* rweights= (const float*)d_in[2];
    const float* w13     = (const float*)d_in[3];
    const float* w2      = (const float*)d_in[4];
    float* out = (float*)d_out;

    // 1) zero output (poisoned by harness) — T*H/4 float4 = 2,097,152
    zero_out_kernel<<<(Tt * Hh / 4) / 256, 256>>>((float4*)out);
    // 2) zero per-expert counters
    zero_cnt_kernel<<<1, 32>>>();
    // 3) build per-expert pair lists
    route_kernel<<<TKp / 256, 256>>>(routing);
    // 4) GEMM1 + silu*up fused: grid (I/64=44, maxRowTiles=128, E=8)
    gemm1_kernel<<<dim3(Ii / 64, TKp / 128, Ee), 256>>>(hidden, w13);
    // 5) GEMM2 + weighted scatter: grid (H/128=8, 128, E=8)
    gemm2_kernel<<<dim3(Hh / 128, TKp / 128, Ee), 256>>>(rweights, w2, out);
}

// round 5
// speedup vs baseline: 3.2444x; 3.2444x over previous
#include <cuda_runtime.h>
#include <cstdint>

#define Tt 8192
#define Kk 2
#define Hh 1024
#define Ii 2816
#define Ee 8
#define TKp (Tt * Kk)
#define I2 (2 * Ii)

// ---- device scratch (no allocation allowed) --------------------------------
__device__ float g_h[(size_t)TKp * Ii];     // 184 MB intermediate h
__device__ float g_pair[(size_t)TKp * Hh];  // 67 MB  per-pair output
__device__ int   g_cnt[Ee];
__device__ int   g_list[Ee * TKp];

// ---- helpers ---------------------------------------------------------------
__device__ __forceinline__ uint32_t f2tf(float f) {
    uint32_t r;
    asm("cvt.rna.tf32.f32 %0, %1;" : "=r"(r) : "f"(f));
    return r;
}
__device__ __forceinline__ void mma8(float* d, const uint32_t* a, const uint32_t* b) {
    asm volatile(
        "mma.sync.aligned.m16n8k8.row.col.f32.tf32.tf32.f32 "
        "{%0,%1,%2,%3},{%4,%5,%6,%7},{%8,%9},{%0,%1,%2,%3};"
        : "+f"(d[0]), "+f"(d[1]), "+f"(d[2]), "+f"(d[3])
        : "r"(a[0]), "r"(a[1]), "r"(a[2]), "r"(a[3]), "r"(b[0]), "r"(b[1]));
}
__device__ __forceinline__ float silu(float g) { return g / (1.f + __expf(-g)); }

#define ASTRIDE 36
#define BSTRIDE 264
#define A_WORDS (128 * ASTRIDE)                  // 4608
#define STAGE_WORDS (A_WORDS + 32 * BSTRIDE)     // 13056 words = 52224 B
#define SMEM_HDR 256                             // words (sp list + pad)
#define SMEM_BYTES ((SMEM_HDR + 2 * STAGE_WORDS) * 4)  // 105472 B

// ---- small kernels ---------------------------------------------------------
__global__ void zero_cnt_kernel() { if (threadIdx.x < Ee) g_cnt[threadIdx.x] = 0; }

__global__ void route_kernel(const int* __restrict__ routing) {
    int p = blockIdx.x * blockDim.x + threadIdx.x;
    if (p >= TKp) return;
    int e = routing[p];
    int pos = atomicAdd(&g_cnt[e], 1);
    g_list[e * TKp + pos] = p;
}

__global__ void reduce_kernel(float4* __restrict__ out) {
    int i = blockIdx.x * blockDim.x + threadIdx.x;
    int t = i >> 8, c = i & 255;
    const float4* p4 = (const float4*)g_pair;
    float4 a = p4[(size_t)(2 * t) * 256 + c];
    float4 b = p4[(size_t)(2 * t + 1) * 256 + c];
    out[i] = make_float4(a.x + b.x, a.y + b.y, a.z + b.z, a.w + b.w);
}

// ---- GEMM1: h = silu(X@Wg) * (X@Wu), gathered rows -------------------------
// Block: 128 rows x 256 B-cols (= 128 h-cols: per warp-col 32 gate + 32 up).
__global__ __launch_bounds__(256)
void gemm1_mma(const float* __restrict__ hidden, const float* __restrict__ w13) {
    const int e = blockIdx.z;
    const int cnt = g_cnt[e];
    const int row0 = blockIdx.y * 128;
    if (row0 >= cnt) return;
    const int c0 = blockIdx.x * 128;          // h-col tile base
    extern __shared__ float smem[];
    int* sp = (int*)smem;
    const int tid = threadIdx.x, lane = tid & 31;
    const int wid = tid >> 5, wm = wid >> 2, wn = wid & 3;

    if (tid < 128) {
        int r = row0 + tid;
        sp[tid] = (r < cnt) ? g_list[e * TKp + r] : -1;
    }
    __syncthreads();

    // A staging: 4 float4/thread; fixed c4a, rows tid>>3 + 32i
    const int c4a = tid & 7;
    const float* aptr[4];
#pragma unroll
    for (int i = 0; i < 4; i++) {
        int p = sp[(tid >> 3) + 32 * i];
        aptr[i] = hidden + (size_t)(p < 0 ? 0 : (p >> 1)) * Hh + c4a * 4;
    }
    // B staging: 8 float4/thread; smem col -> global col remap (gate/up interleave)
    const int c4b = tid & 63;
    int j0 = c4b * 4, wc = j0 >> 6, jj = j0 & 63;
    int gcol = (jj < 32) ? (c0 + wc * 32 + jj) : (Ii + c0 + wc * 32 + (jj - 32));
    const float* bptr = w13 + (size_t)e * Hh * I2 + (size_t)(tid >> 6) * I2 + gcol;

    float* buf0 = smem + SMEM_HDR;
    float* buf1 = buf0 + STAGE_WORDS;

    float acc[4][8][4];
#pragma unroll
    for (int mi = 0; mi < 4; mi++)
#pragma unroll
        for (int ni = 0; ni < 8; ni++)
#pragma unroll
            for (int c = 0; c < 4; c++) acc[mi][ni][c] = 0.f;

    float4 ra[4], rb[8];
    auto LDGALL = [&](int s) {
        int k0 = s * 32;
#pragma unroll
        for (int i = 0; i < 4; i++) ra[i] = *(const float4*)(aptr[i] + k0);
#pragma unroll
        for (int i = 0; i < 8; i++) rb[i] = *(const float4*)(bptr + (size_t)(k0 + 4 * i) * I2);
    };
    auto STSALL = [&](float* S) {
        uint32_t* Sw = (uint32_t*)S;
#pragma unroll
        for (int i = 0; i < 4; i++) {
            uint4 v = { f2tf(ra[i].x), f2tf(ra[i].y), f2tf(ra[i].z), f2tf(ra[i].w) };
            *(uint4*)(Sw + ((tid >> 3) + 32 * i) * ASTRIDE + c4a * 4) = v;
        }
#pragma unroll
        for (int i = 0; i < 8; i++) {
            uint4 v = { f2tf(rb[i].x), f2tf(rb[i].y), f2tf(rb[i].z), f2tf(rb[i].w) };
            *(uint4*)(Sw + A_WORDS + ((tid >> 6) + 4 * i) * BSTRIDE + c4b * 4) = v;
        }
    };
    auto COMPUTE = [&](const float* S) {
        const uint32_t* Aw = (const uint32_t*)S;
        const uint32_t* Bw = Aw + A_WORDS;
#pragma unroll
        for (int ks = 0; ks < 4; ks++) {
            uint32_t af[4][4], bf[8][2];
            int kk = ks * 8 + (lane & 3);
#pragma unroll
            for (int mi = 0; mi < 4; mi++) {
                int r = wm * 64 + mi * 16 + (lane >> 2);
                af[mi][0] = Aw[r * ASTRIDE + kk];
                af[mi][1] = Aw[(r + 8) * ASTRIDE + kk];
                af[mi][2] = Aw[r * ASTRIDE + kk + 4];
                af[mi][3] = Aw[(r + 8) * ASTRIDE + kk + 4];
            }
#pragma unroll
            for (int ni = 0; ni < 8; ni++) {
                int n = wn * 64 + ni * 8 + (lane >> 2);
                bf[ni][0] = Bw[kk * BSTRIDE + n];
                bf[ni][1] = Bw[(kk + 4) * BSTRIDE + n];
            }
#pragma unroll
            for (int mi = 0; mi < 4; mi++)
#pragma unroll
                for (int ni = 0; ni < 8; ni++) mma8(acc[mi][ni], af[mi], bf[ni]);
        }
    };

    const int S = Hh / 32;  // 32
    LDGALL(0); STSALL(buf0);
    __syncthreads();
    for (int s = 0; s < S; s++) {
        if (s + 1 < S) LDGALL(s + 1);
        COMPUTE((s & 1) ? buf1 : buf0);
        if (s + 1 < S) STSALL(((s + 1) & 1) ? buf1 : buf0);
        __syncthreads();
    }

    // epilogue: pair gate (ni) with up (ni+4), fuse silu in registers
#pragma unroll
    for (int mi = 0; mi < 4; mi++) {
        int r0 = wm * 64 + mi * 16 + (lane >> 2);
        int p0 = sp[r0], p1 = sp[r0 + 8];
#pragma unroll
        for (int ni = 0; ni < 4; ni++) {
            int col = c0 + wn * 32 + ni * 8 + (lane & 3) * 2;
            if (p0 >= 0) {
                float2 h2;
                h2.x = silu(acc[mi][ni][0]) * acc[mi][ni + 4][0];
                h2.y = silu(acc[mi][ni][1]) * acc[mi][ni + 4][1];
                *(float2*)(g_h + (size_t)p0 * Ii + col) = h2;
            }
            if (p1 >= 0) {
                float2 h2;
                h2.x = silu(acc[mi][ni][2]) * acc[mi][ni + 4][2];
                h2.y = silu(acc[mi][ni][3]) * acc[mi][ni + 4][3];
                *(float2*)(g_h + (size_t)p1 * Ii + col) = h2;
            }
        }
    }
}

// ---- GEMM2: pair_out = rw * (h @ W2), gathered rows -------------------------
__global__ __launch_bounds__(256)
void gemm2_mma(const float* __restrict__ rw, const float* __restrict__ w2) {
    const int e = blockIdx.z;
    const int cnt = g_cnt[e];
    const int row0 = blockIdx.y * 128;
    if (row0 >= cnt) return;
    const int nc0 = blockIdx.x * 256;
    extern __shared__ float smem[];
    int* sp = (int*)smem;
    const int tid = threadIdx.x, lane = tid & 31;
    const int wid = tid >> 5, wm = wid >> 2, wn = wid & 3;

    if (tid < 128) {
        int r = row0 + tid;
        sp[tid] = (r < cnt) ? g_list[e * TKp + r] : -1;
    }
    __syncthreads();

    const int c4a = tid & 7;
    const float* aptr[4];
#pragma unroll
    for (int i = 0; i < 4; i++) {
        int p = sp[(tid >> 3) + 32 * i];
        aptr[i] = g_h + (size_t)(p < 0 ? 0 : p) * Ii + c4a * 4;
    }
    const int c4b = tid & 63;
    const float* bptr = w2 + (size_t)e * Ii * Hh + (size_t)(tid >> 6) * Hh + nc0 + c4b * 4;

    float* buf0 = smem + SMEM_HDR;
    float* buf1 = buf0 + STAGE_WORDS;

    float acc[4][8][4];
#pragma unroll
    for (int mi = 0; mi < 4; mi++)
#pragma unroll
        for (int ni = 0; ni < 8; ni++)
#pragma unroll
            for (int c = 0; c < 4; c++) acc[mi][ni][c] = 0.f;

    float4 ra[4], rb[8];
    auto LDGALL = [&](int s) {
        int k0 = s * 32;
#pragma unroll
        for (int i = 0; i < 4; i++) ra[i] = *(const float4*)(aptr[i] + k0);
#pragma unroll
        for (int i = 0; i < 8; i++) rb[i] = *(const float4*)(bptr + (size_t)(k0 + 4 * i) * Hh);
    };
    auto STSALL = [&](float* S) {
        uint32_t* Sw = (uint32_t*)S;
#pragma unroll
        for (int i = 0; i < 4; i++) {
            uint4 v = { f2tf(ra[i].x), f2tf(ra[i].y), f2tf(ra[i].z), f2tf(ra[i].w) };
            *(uint4*)(Sw + ((tid >> 3) + 32 * i) * ASTRIDE + c4a * 4) = v;
        }
#pragma unroll
        for (int i = 0; i < 8; i++) {
            uint4 v = { f2tf(rb[i].x), f2tf(rb[i].y), f2tf(rb[i].z), f2tf(rb[i].w) };
            *(uint4*)(Sw + A_WORDS + ((tid >> 6) + 4 * i) * BSTRIDE + c4b * 4) = v;
        }
    };
    auto COMPUTE = [&](const float* S) {
        const uint32_t* Aw = (const uint32_t*)S;
        const uint32_t* Bw = Aw + A_WORDS;
#pragma unroll
        for (int ks = 0; ks < 4; ks++) {
            uint32_t af[4][4], bf[8][2];
            int kk = ks * 8 + (lane & 3);
#pragma unroll
            for (int mi = 0; mi < 4; mi++) {
                int r = wm * 64 + mi * 16 + (lane >> 2);
                af[mi][0] = Aw[r * ASTRIDE + kk];
                af[mi][1] = Aw[(r + 8) * ASTRIDE + kk];
                af[mi][2] = Aw[r * ASTRIDE + kk + 4];
                af[mi][3] = Aw[(r + 8) * ASTRIDE + kk + 4];
            }
#pragma unroll
            for (int ni = 0; ni < 8; ni++) {
                int n = wn * 64 + ni * 8 + (lane >> 2);
                bf[ni][0] = Bw[kk * BSTRIDE + n];
                bf[ni][1] = Bw[(kk + 4) * BSTRIDE + n];
            }
#pragma unroll
            for (int mi = 0; mi < 4; mi++)
#pragma unroll
                for (int ni = 0; ni < 8; ni++) mma8(acc[mi][ni], af[mi], bf[ni]);
        }
    };

    const int S = Ii / 32;  // 88
    LDGALL(0); STSALL(buf0);
    __syncthreads();
    for (int s = 0; s < S; s++) {
        if (s + 1 < S) LDGALL(s + 1);
        COMPUTE((s & 1) ? buf1 : buf0);
        if (s + 1 < S) STSALL(((s + 1) & 1) ? buf1 : buf0);
        __syncthreads();
    }

    // epilogue: scale by router weight, per-pair store (no atomics)
#pragma unroll
    for (int mi = 0; mi < 4; mi++) {
        int r0 = wm * 64 + mi * 16 + (lane >> 2);
        int p0 = sp[r0], p1 = sp[r0 + 8];
        float cv0 = (p0 >= 0) ? rw[p0] : 0.f;
        float cv1 = (p1 >= 0) ? rw[p1] : 0.f;
#pragma unroll
        for (int ni = 0; ni < 8; ni++) {
            int col = nc0 + wn * 64 + ni * 8 + (lane & 3) * 2;
            if (p0 >= 0) {
                float2 o = { cv0 * acc[mi][ni][0], cv0 * acc[mi][ni][1] };
                *(float2*)(g_pair + (size_t)p0 * Hh + col) = o;
            }
            if (p1 >= 0) {
                float2 o = { cv1 * acc[mi][ni][2], cv1 * acc[mi][ni][3] };
                *(float2*)(g_pair + (size_t)p1 * Hh + col) = o;
            }
        }
    }
}

// ---------------------------------------------------------------------------
extern "C" void kernel_launch(void* const* d_in, const int* in_sizes, int n_in,
                              void* d_out, int out_size) {
    const float* hidden   = (const float*)d_in[0];
    const int*   routing  = (const int*)d_in[1];
    const float* rweights = (const float*)d_in[2];
    const float* w13      = (const float*)d_in[3];
    const float* w2       = (const float*)d_in[4];

    cudaFuncSetAttribute(gemm1_mma, cudaFuncAttributeMaxDynamicSharedMemorySize, SMEM_BYTES);
    cudaFuncSetAttribute(gemm2_mma, cudaFuncAttributeMaxDynamicSharedMemorySize, SMEM_BYTES);

    zero_cnt_kernel<<<1, 32>>>();
    route_kernel<<<TKp / 256, 256>>>(routing);
    // x = N tile (fast-varying for L2 A-reuse), y = M tile, z = expert
    gemm1_mma<<<dim3(Ii / 128, TKp / 128, Ee), 256, SMEM_BYTES>>>(hidden, w13);
    gemm2_mma<<<dim3(Hh / 256, TKp / 128, Ee), 256, SMEM_BYTES>>>(rweights, w2);
    reduce_kernel<<<(Tt * Hh / 4) / 256, 256>>>((float4*)d_out);
}